// round 1
// baseline (speedup 1.0000x reference)
#include <cuda_runtime.h>

#define Nn 50000
#define Ee 800000
#define Hh 4

// ---------------- persistent scratch (no allocations allowed) ----------------
__device__ float g_h[Nn * 256];     // pre-aggregation features (max layer width 256)
__device__ float g_act[Nn * 256];   // post-aggregation activations
__device__ float g_as[Nn * Hh];     // per-node per-head alpha_src
__device__ float g_ad[Nn * Hh];     // per-node per-head alpha_dst
__device__ int   g_counts[Nn];
__device__ int   g_starts[Nn];
__device__ int   g_cursor[Nn];
__device__ int   g_csr[Ee];
__device__ int   g_bsum[64];

// ---------------- CSR build ----------------
__global__ void zero_k() {
    int i = blockIdx.x * blockDim.x + threadIdx.x;
    if (i < Nn) { g_counts[i] = 0; g_cursor[i] = 0; }
}

__global__ void hist_k(const int* __restrict__ ei) {
    int e = blockIdx.x * blockDim.x + threadIdx.x;
    if (e < Ee) atomicAdd(&g_counts[ei[Ee + e]], 1);
}

__global__ void scan1_k() {
    __shared__ int sh[1024];
    int t = threadIdx.x;
    int i = blockIdx.x * 1024 + t;
    int v = (i < Nn) ? g_counts[i] : 0;
    sh[t] = v;
    __syncthreads();
    #pragma unroll
    for (int off = 1; off < 1024; off <<= 1) {
        int x = (t >= off) ? sh[t - off] : 0;
        __syncthreads();
        sh[t] += x;
        __syncthreads();
    }
    if (i < Nn) g_starts[i] = sh[t];       // inclusive scan, fixed up in scan3
    if (t == 1023) g_bsum[blockIdx.x] = sh[1023];
}

__global__ void scan2_k() {
    __shared__ int sh[64];
    int t = threadIdx.x;
    const int NB = (Nn + 1023) / 1024;     // 49
    if (t < NB) sh[t] = g_bsum[t];
    __syncthreads();
    if (t == 0) {
        int s = 0;
        for (int i = 0; i < NB; i++) { s += sh[i]; sh[i] = s; }
    }
    __syncthreads();
    if (t < NB) g_bsum[t] = sh[t];
}

__global__ void scan3_k() {
    int i = blockIdx.x * 1024 + threadIdx.x;
    if (i >= Nn) return;
    int off = (blockIdx.x > 0) ? g_bsum[blockIdx.x - 1] : 0;
    g_starts[i] = g_starts[i] - g_counts[i] + off;   // exclusive start
}

__global__ void fill_k(const int* __restrict__ ei) {
    int e = blockIdx.x * blockDim.x + threadIdx.x;
    if (e >= Ee) return;
    int src = ei[e];
    int dst = ei[Ee + e];
    int pos = g_starts[dst] + atomicAdd(&g_cursor[dst], 1);
    g_csr[pos] = src;
}

// ---------------- GEMM: h = A @ W  (A: [N,IN_], W: [IN_,OUT_] row-major) ----------------
template <int IN_, int OUT_, int TM>
__global__ void __launch_bounds__(OUT_) gemm_k(const float* __restrict__ A,
                                               const float* __restrict__ W) {
    __shared__ float s[TM * IN_];
    int base = blockIdx.x * TM;
    for (int idx = threadIdx.x; idx < TM * IN_; idx += OUT_) {
        int row = base + idx / IN_;
        s[idx] = (row < Nn) ? A[row * IN_ + (idx % IN_)] : 0.f;
    }
    __syncthreads();
    int col = threadIdx.x;
    float acc[TM];
    #pragma unroll
    for (int r = 0; r < TM; r++) acc[r] = 0.f;

    for (int k = 0; k < IN_; k += 4) {
        float w0 = W[(k + 0) * OUT_ + col];
        float w1 = W[(k + 1) * OUT_ + col];
        float w2 = W[(k + 2) * OUT_ + col];
        float w3 = W[(k + 3) * OUT_ + col];
        #pragma unroll
        for (int r = 0; r < TM; r++) {
            float4 a = *reinterpret_cast<const float4*>(&s[r * IN_ + k]);
            acc[r] = fmaf(a.x, w0, acc[r]);
            acc[r] = fmaf(a.y, w1, acc[r]);
            acc[r] = fmaf(a.z, w2, acc[r]);
            acc[r] = fmaf(a.w, w3, acc[r]);
        }
    }
    #pragma unroll
    for (int r = 0; r < TM; r++) {
        int row = base + r;
        if (row < Nn) g_h[row * OUT_ + col] = acc[r];
    }
}

// ---------------- per-node attention logits: alpha_s/alpha_d ----------------
template <int C>
__global__ void alpha_k(const float* __restrict__ a_src, const float* __restrict__ a_dst) {
    int i = blockIdx.x * blockDim.x + threadIdx.x;
    if (i >= Nn * Hh) return;
    int node = i >> 2, head = i & 3;
    const float* hp = &g_h[node * (Hh * C) + head * C];
    float ss = 0.f, sd = 0.f;
    #pragma unroll
    for (int c = 0; c < C; c++) {
        float v = hp[c];
        ss = fmaf(v, a_src[head * C + c], ss);
        sd = fmaf(v, a_dst[head * C + c], sd);
    }
    g_as[i] = ss;
    g_ad[i] = sd;
}

// ---------------- per-dst softmax + aggregation (atomic-free via CSR) ----------------
template <int C>
__global__ void __launch_bounds__(256) agg_k(const float* __restrict__ bias) {
    constexpr int HC  = Hh * C;
    constexpr int NPB = 256 / HC;
    int g    = threadIdx.x % HC;
    int node = blockIdx.x * NPB + threadIdx.x / HC;
    if (node >= Nn) return;
    int head = g / C;

    float ad = g_ad[node * Hh + head];

    // implicit self-loop
    float e = g_as[node * Hh + head] + ad;
    e = (e < 0.f) ? 0.2f * e : e;
    float p     = __expf(e);
    float denom = p;
    float acc   = p * g_h[node * HC + g];

    int start = g_starts[node];
    int cnt   = g_counts[node];
    for (int j = 0; j < cnt; j++) {
        int src = g_csr[start + j];
        float ev = g_as[src * Hh + head] + ad;
        ev = (ev < 0.f) ? 0.2f * ev : ev;
        float pv = __expf(ev);
        denom += pv;
        acc = fmaf(pv, g_h[src * HC + g], acc);
    }
    float val = acc / denom + bias[g];
    g_act[node * HC + g] = (val > 0.f) ? val : expm1f(val);   // ELU
}

// ---------------- fused MLP head: 256 -> 32 -> 64 -> 1 ----------------
__global__ void __launch_bounds__(256) mlp_k(const float* __restrict__ Wr,  const float* __restrict__ br,
                                             const float* __restrict__ Wf1, const float* __restrict__ bf1,
                                             const float* __restrict__ Wf2, const float* __restrict__ bf2,
                                             float* __restrict__ out) {
    __shared__ float sin_[8 * 256];
    __shared__ float smid[8 * 32];
    int w = threadIdx.x / 32, lane = threadIdx.x % 32;
    int nodeBase = blockIdx.x * 8;

    for (int idx = threadIdx.x; idx < 8 * 256; idx += 256) {
        int node = nodeBase + idx / 256;
        sin_[idx] = (node < Nn) ? g_act[node * 256 + (idx % 256)] : 0.f;
    }
    __syncthreads();

    int node = nodeBase + w;
    // 256 -> 32
    float acc = br[lane];
    #pragma unroll 4
    for (int k = 0; k < 256; k++) acc = fmaf(sin_[w * 256 + k], Wr[k * 32 + lane], acc);
    acc = (acc > 0.f) ? acc : expm1f(acc);
    smid[w * 32 + lane] = acc;
    __syncwarp();
    // 32 -> 64 (two columns per lane)
    float f0 = bf1[lane], f1 = bf1[lane + 32];
    #pragma unroll
    for (int k = 0; k < 32; k++) {
        float m = smid[w * 32 + k];
        f0 = fmaf(m, Wf1[k * 64 + lane],      f0);
        f1 = fmaf(m, Wf1[k * 64 + lane + 32], f1);
    }
    f0 = (f0 > 0.f) ? f0 : expm1f(f0);
    f1 = (f1 > 0.f) ? f1 : expm1f(f1);
    // 64 -> 1
    float part = f0 * Wf2[lane] + f1 * Wf2[lane + 32];
    #pragma unroll
    for (int off = 16; off; off >>= 1) part += __shfl_xor_sync(0xffffffff, part, off);
    if (lane == 0 && node < Nn) out[node] = part + bf2[0];
}

// ---------------- launch ----------------
extern "C" void kernel_launch(void* const* d_in, const int* in_sizes, int n_in,
                              void* d_out, int out_size) {
    const float* x   = (const float*)d_in[0];
    const int*   ei  = (const int*)  d_in[1];
    // d_in[2] = edge_attr (unused)
    const float* W1  = (const float*)d_in[3];
    const float* as1 = (const float*)d_in[4];
    const float* ad1 = (const float*)d_in[5];
    const float* b1  = (const float*)d_in[6];
    const float* W2  = (const float*)d_in[7];
    const float* as2 = (const float*)d_in[8];
    const float* ad2 = (const float*)d_in[9];
    const float* b2  = (const float*)d_in[10];
    const float* W3  = (const float*)d_in[11];
    const float* as3 = (const float*)d_in[12];
    const float* ad3 = (const float*)d_in[13];
    const float* b3  = (const float*)d_in[14];
    const float* W4  = (const float*)d_in[15];
    const float* as4 = (const float*)d_in[16];
    const float* ad4 = (const float*)d_in[17];
    const float* b4  = (const float*)d_in[18];
    const float* Wr  = (const float*)d_in[19];
    const float* br  = (const float*)d_in[20];
    const float* Wf1 = (const float*)d_in[21];
    const float* bf1 = (const float*)d_in[22];
    const float* Wf2 = (const float*)d_in[23];
    const float* bf2 = (const float*)d_in[24];
    float* out = (float*)d_out;

    float* actp = nullptr;
    cudaGetSymbolAddress((void**)&actp, g_act);

    const int NB_SCAN = (Nn + 1023) / 1024;   // 49

    // CSR build (same graph for all 4 layers)
    zero_k<<<(Nn + 255) / 256, 256>>>();
    hist_k<<<(Ee + 255) / 256, 256>>>(ei);
    scan1_k<<<NB_SCAN, 1024>>>();
    scan2_k<<<1, 64>>>();
    scan3_k<<<NB_SCAN, 1024>>>();
    fill_k<<<(Ee + 255) / 256, 256>>>(ei);

    const int GB = (Nn + 31) / 32;            // gemm blocks (TM=32)
    const int AB = (Nn * Hh + 255) / 256;     // alpha blocks

    // Layer 1: 128 -> 4x8
    gemm_k<128, 32, 32><<<GB, 32>>>(x, W1);
    alpha_k<8><<<AB, 256>>>(as1, ad1);
    agg_k<8><<<(Nn + 7) / 8, 256>>>(b1);

    // Layer 2: 32 -> 4x16
    gemm_k<32, 64, 32><<<GB, 64>>>(actp, W2);
    alpha_k<16><<<AB, 256>>>(as2, ad2);
    agg_k<16><<<(Nn + 3) / 4, 256>>>(b2);

    // Layer 3: 64 -> 4x32
    gemm_k<64, 128, 32><<<GB, 128>>>(actp, W3);
    alpha_k<32><<<AB, 256>>>(as3, ad3);
    agg_k<32><<<(Nn + 1) / 2, 256>>>(b3);

    // Layer 4: 128 -> 4x64
    gemm_k<128, 256, 32><<<GB, 256>>>(actp, W4);
    alpha_k<64><<<AB, 256>>>(as4, ad4);
    agg_k<64><<<Nn, 256>>>(b4);

    // MLP head
    mlp_k<<<(Nn + 7) / 8, 256>>>(Wr, br, Wf1, bf1, Wf2, bf2, out);
}

// round 2
// speedup vs baseline: 1.5355x; 1.5355x over previous
#include <cuda_runtime.h>

#define Nn 50000
#define Ee 800000
#define Hh 4

// ---------------- persistent scratch (no allocations allowed) ----------------
__device__ float g_h[Nn * 256];     // pre-aggregation features (max layer width 256)
__device__ float g_act[Nn * 256];   // post-aggregation activations
__device__ float g_as[Nn * Hh];     // per-node per-head alpha_src
__device__ float g_ad[Nn * Hh];     // per-node per-head alpha_dst
__device__ float g_pv[Ee * Hh];     // per-edge per-head softmax numerator (CSR order)
__device__ int   g_counts[Nn];
__device__ int   g_starts[Nn];
__device__ int   g_cursor[Nn];
__device__ int   g_csr[Ee];         // src node per CSR slot
__device__ int   g_edst[Ee];        // dst node per CSR slot
__device__ int   g_bsum[64];

// ---------------- packed f32x2 helpers ----------------
typedef unsigned long long u64t;

__device__ __forceinline__ void ffma2(u64t& acc, u64t a, u64t b) {
    asm("fma.rn.f32x2 %0, %1, %2, %0;" : "+l"(acc) : "l"(a), "l"(b));
}
__device__ __forceinline__ u64t dup2(float x) {
    u64t r; asm("mov.b64 %0, {%1, %1};" : "=l"(r) : "f"(x)); return r;
}
__device__ __forceinline__ float2 unpack2(u64t v) {
    float2 r; asm("mov.b64 {%0, %1}, %2;" : "=f"(r.x), "=f"(r.y) : "l"(v)); return r;
}

// ---------------- CSR build ----------------
__global__ void zero_k() {
    int i = blockIdx.x * blockDim.x + threadIdx.x;
    if (i < Nn) { g_counts[i] = 0; g_cursor[i] = 0; }
}

__global__ void hist_k(const int* __restrict__ ei) {
    int e = blockIdx.x * blockDim.x + threadIdx.x;
    if (e < Ee) atomicAdd(&g_counts[ei[Ee + e]], 1);
}

__global__ void scan1_k() {
    __shared__ int sh[1024];
    int t = threadIdx.x;
    int i = blockIdx.x * 1024 + t;
    int v = (i < Nn) ? g_counts[i] : 0;
    sh[t] = v;
    __syncthreads();
    #pragma unroll
    for (int off = 1; off < 1024; off <<= 1) {
        int x = (t >= off) ? sh[t - off] : 0;
        __syncthreads();
        sh[t] += x;
        __syncthreads();
    }
    if (i < Nn) g_starts[i] = sh[t];       // inclusive; fixed up in scan3
    if (t == 1023) g_bsum[blockIdx.x] = sh[1023];
}

__global__ void scan2_k() {
    __shared__ int sh[64];
    int t = threadIdx.x;
    const int NB = (Nn + 1023) / 1024;     // 49
    if (t < NB) sh[t] = g_bsum[t];
    __syncthreads();
    if (t == 0) {
        int s = 0;
        for (int i = 0; i < NB; i++) { s += sh[i]; sh[i] = s; }
    }
    __syncthreads();
    if (t < NB) g_bsum[t] = sh[t];
}

__global__ void scan3_k() {
    int i = blockIdx.x * 1024 + threadIdx.x;
    if (i >= Nn) return;
    int off = (blockIdx.x > 0) ? g_bsum[blockIdx.x - 1] : 0;
    g_starts[i] = g_starts[i] - g_counts[i] + off;   // exclusive start
}

__global__ void fill_k(const int* __restrict__ ei) {
    int e = blockIdx.x * blockDim.x + threadIdx.x;
    if (e >= Ee) return;
    int src = ei[e];
    int dst = ei[Ee + e];
    int pos = g_starts[dst] + atomicAdd(&g_cursor[dst], 1);
    g_csr[pos]  = src;
    g_edst[pos] = dst;
}

// ---------------- GEMM: h = A @ W via packed f32x2 ----------------
// A: [N, IN_] row-major, W: [IN_, OUT_] row-major, out -> g_h [N, OUT_]
// Block: TM=64 rows. Thread tile: RT=8 rows (4 packed pairs) x CT=4 cols.
template <int IN_, int OUT_>
__global__ void __launch_bounds__((OUT_ / 4) * 8) gemm_k(const float* __restrict__ A,
                                                         const float* __restrict__ W) {
    constexpr int TM = 64;
    constexpr int CG = OUT_ / 4;           // col groups
    __shared__ float sA[IN_ * TM];         // transposed: sA[k*TM + r]

    int base = blockIdx.x * TM;
    int nt = CG * 8;

    // cooperative load: A rows -> transposed smem (zero-pad OOB rows)
    for (int idx = threadIdx.x; idx < TM * (IN_ / 4); idx += nt) {
        int r  = idx / (IN_ / 4);
        int k4 = (idx % (IN_ / 4)) * 4;
        int row = base + r;
        float4 v = (row < Nn) ? *reinterpret_cast<const float4*>(&A[row * IN_ + k4])
                              : make_float4(0.f, 0.f, 0.f, 0.f);
        sA[(k4 + 0) * TM + r] = v.x;
        sA[(k4 + 1) * TM + r] = v.y;
        sA[(k4 + 2) * TM + r] = v.z;
        sA[(k4 + 3) * TM + r] = v.w;
    }
    __syncthreads();

    int cg = threadIdx.x % CG;             // which 4-col group
    int rg = threadIdx.x / CG;             // which 8-row group
    int r0 = rg * 8;
    int c0 = cg * 4;

    u64t acc[4][4];                        // [row-pair][col]
    #pragma unroll
    for (int p = 0; p < 4; p++)
        #pragma unroll
        for (int c = 0; c < 4; c++) acc[p][c] = 0ull;

    #pragma unroll 4
    for (int k = 0; k < IN_; k++) {
        u64t a0 = *reinterpret_cast<const u64t*>(&sA[k * TM + r0 + 0]);
        u64t a1 = *reinterpret_cast<const u64t*>(&sA[k * TM + r0 + 2]);
        u64t a2 = *reinterpret_cast<const u64t*>(&sA[k * TM + r0 + 4]);
        u64t a3 = *reinterpret_cast<const u64t*>(&sA[k * TM + r0 + 6]);
        float4 w = *reinterpret_cast<const float4*>(&W[k * OUT_ + c0]);
        u64t w0 = dup2(w.x), w1 = dup2(w.y), w2 = dup2(w.z), w3 = dup2(w.w);
        ffma2(acc[0][0], a0, w0); ffma2(acc[0][1], a0, w1);
        ffma2(acc[0][2], a0, w2); ffma2(acc[0][3], a0, w3);
        ffma2(acc[1][0], a1, w0); ffma2(acc[1][1], a1, w1);
        ffma2(acc[1][2], a1, w2); ffma2(acc[1][3], a1, w3);
        ffma2(acc[2][0], a2, w0); ffma2(acc[2][1], a2, w1);
        ffma2(acc[2][2], a2, w2); ffma2(acc[2][3], a2, w3);
        ffma2(acc[3][0], a3, w0); ffma2(acc[3][1], a3, w1);
        ffma2(acc[3][2], a3, w2); ffma2(acc[3][3], a3, w3);
    }

    #pragma unroll
    for (int p = 0; p < 4; p++) {
        float2 v0 = unpack2(acc[p][0]);
        float2 v1 = unpack2(acc[p][1]);
        float2 v2 = unpack2(acc[p][2]);
        float2 v3 = unpack2(acc[p][3]);
        int row = base + r0 + 2 * p;
        if (row < Nn)
            *reinterpret_cast<float4*>(&g_h[row * OUT_ + c0]) =
                make_float4(v0.x, v1.x, v2.x, v3.x);
        if (row + 1 < Nn)
            *reinterpret_cast<float4*>(&g_h[(row + 1) * OUT_ + c0]) =
                make_float4(v0.y, v1.y, v2.y, v3.y);
    }
}

// ---------------- per-node attention logits ----------------
template <int C>
__global__ void alpha_k(const float* __restrict__ a_src, const float* __restrict__ a_dst) {
    int i = blockIdx.x * blockDim.x + threadIdx.x;
    if (i >= Nn * Hh) return;
    int node = i >> 2, head = i & 3;
    const float4* hp = reinterpret_cast<const float4*>(&g_h[node * (Hh * C) + head * C]);
    const float4* sp = reinterpret_cast<const float4*>(&a_src[head * C]);
    const float4* dp = reinterpret_cast<const float4*>(&a_dst[head * C]);
    float ss = 0.f, sd = 0.f;
    #pragma unroll
    for (int c = 0; c < C / 4; c++) {
        float4 v = hp[c];
        float4 s = __ldg(&sp[c]);
        float4 d = __ldg(&dp[c]);
        ss = fmaf(v.x, s.x, fmaf(v.y, s.y, fmaf(v.z, s.z, fmaf(v.w, s.w, ss))));
        sd = fmaf(v.x, d.x, fmaf(v.y, d.y, fmaf(v.z, d.z, fmaf(v.w, d.w, sd))));
    }
    g_as[i] = ss;
    g_ad[i] = sd;
}

// ---------------- per-edge softmax numerators (all 4 heads) ----------------
__global__ void epv_k() {
    int p = blockIdx.x * blockDim.x + threadIdx.x;
    if (p >= Ee) return;
    int src = g_csr[p];
    int dst = g_edst[p];
    float4 s = *reinterpret_cast<const float4*>(&g_as[src * Hh]);
    float4 d = *reinterpret_cast<const float4*>(&g_ad[dst * Hh]);
    float4 e = make_float4(s.x + d.x, s.y + d.y, s.z + d.z, s.w + d.w);
    e.x = (e.x < 0.f) ? 0.2f * e.x : e.x;
    e.y = (e.y < 0.f) ? 0.2f * e.y : e.y;
    e.z = (e.z < 0.f) ? 0.2f * e.z : e.z;
    e.w = (e.w < 0.f) ? 0.2f * e.w : e.w;
    *reinterpret_cast<float4*>(&g_pv[p * Hh]) =
        make_float4(__expf(e.x), __expf(e.y), __expf(e.z), __expf(e.w));
}

// ---------------- per-dst aggregation (atomic-free, float4 channels) ----------------
template <int C>
__global__ void __launch_bounds__(256) agg_k(const float* __restrict__ bias) {
    constexpr int HC  = Hh * C;
    constexpr int TPN = HC / 4;            // threads per node
    constexpr int NPB = 256 / TPN;
    int t    = threadIdx.x % TPN;
    int node = blockIdx.x * NPB + threadIdx.x / TPN;
    if (node >= Nn) return;
    int g4   = t * 4;                      // channel offset
    int head = g4 / C;

    // implicit self-loop
    float es = g_as[node * Hh + head] + g_ad[node * Hh + head];
    es = (es < 0.f) ? 0.2f * es : es;
    float pl = __expf(es);
    float denom = pl;
    float4 hv = *reinterpret_cast<const float4*>(&g_h[node * HC + g4]);
    float4 acc = make_float4(pl * hv.x, pl * hv.y, pl * hv.z, pl * hv.w);

    int start = g_starts[node];
    int cnt   = g_counts[node];
    #pragma unroll 4
    for (int j = 0; j < cnt; j++) {
        int   src = g_csr[start + j];
        float pv  = g_pv[(start + j) * Hh + head];
        float4 h  = *reinterpret_cast<const float4*>(&g_h[src * HC + g4]);
        denom += pv;
        acc.x = fmaf(pv, h.x, acc.x);
        acc.y = fmaf(pv, h.y, acc.y);
        acc.z = fmaf(pv, h.z, acc.z);
        acc.w = fmaf(pv, h.w, acc.w);
    }
    float inv = 1.0f / denom;
    float4 b = *reinterpret_cast<const float4*>(&bias[g4]);
    float4 o;
    o.x = acc.x * inv + b.x;
    o.y = acc.y * inv + b.y;
    o.z = acc.z * inv + b.z;
    o.w = acc.w * inv + b.w;
    o.x = (o.x > 0.f) ? o.x : expm1f(o.x);
    o.y = (o.y > 0.f) ? o.y : expm1f(o.y);
    o.z = (o.z > 0.f) ? o.z : expm1f(o.z);
    o.w = (o.w > 0.f) ? o.w : expm1f(o.w);
    *reinterpret_cast<float4*>(&g_act[node * HC + g4]) = o;
}

// ---------------- fused MLP head: 256 -> 32 -> 64 -> 1 ----------------
__global__ void __launch_bounds__(256) mlp_k(const float* __restrict__ Wr,  const float* __restrict__ br,
                                             const float* __restrict__ Wf1, const float* __restrict__ bf1,
                                             const float* __restrict__ Wf2, const float* __restrict__ bf2,
                                             float* __restrict__ out) {
    __shared__ float sin_[8 * 256];
    __shared__ float smid[8 * 32];
    int w = threadIdx.x / 32, lane = threadIdx.x % 32;
    int nodeBase = blockIdx.x * 8;

    for (int idx = threadIdx.x; idx < 8 * 256; idx += 256) {
        int node = nodeBase + idx / 256;
        sin_[idx] = (node < Nn) ? g_act[node * 256 + (idx % 256)] : 0.f;
    }
    __syncthreads();

    int node = nodeBase + w;
    float acc = br[lane];
    #pragma unroll 4
    for (int k = 0; k < 256; k++) acc = fmaf(sin_[w * 256 + k], Wr[k * 32 + lane], acc);
    acc = (acc > 0.f) ? acc : expm1f(acc);
    smid[w * 32 + lane] = acc;
    __syncwarp();
    float f0 = bf1[lane], f1 = bf1[lane + 32];
    #pragma unroll
    for (int k = 0; k < 32; k++) {
        float m = smid[w * 32 + k];
        f0 = fmaf(m, Wf1[k * 64 + lane],      f0);
        f1 = fmaf(m, Wf1[k * 64 + lane + 32], f1);
    }
    f0 = (f0 > 0.f) ? f0 : expm1f(f0);
    f1 = (f1 > 0.f) ? f1 : expm1f(f1);
    float part = f0 * Wf2[lane] + f1 * Wf2[lane + 32];
    #pragma unroll
    for (int off = 16; off; off >>= 1) part += __shfl_xor_sync(0xffffffff, part, off);
    if (lane == 0 && node < Nn) out[node] = part + bf2[0];
}

// ---------------- launch ----------------
extern "C" void kernel_launch(void* const* d_in, const int* in_sizes, int n_in,
                              void* d_out, int out_size) {
    const float* x   = (const float*)d_in[0];
    const int*   ei  = (const int*)  d_in[1];
    const float* W1  = (const float*)d_in[3];
    const float* as1 = (const float*)d_in[4];
    const float* ad1 = (const float*)d_in[5];
    const float* b1  = (const float*)d_in[6];
    const float* W2  = (const float*)d_in[7];
    const float* as2 = (const float*)d_in[8];
    const float* ad2 = (const float*)d_in[9];
    const float* b2  = (const float*)d_in[10];
    const float* W3  = (const float*)d_in[11];
    const float* as3 = (const float*)d_in[12];
    const float* ad3 = (const float*)d_in[13];
    const float* b3  = (const float*)d_in[14];
    const float* W4  = (const float*)d_in[15];
    const float* as4 = (const float*)d_in[16];
    const float* ad4 = (const float*)d_in[17];
    const float* b4  = (const float*)d_in[18];
    const float* Wr  = (const float*)d_in[19];
    const float* br  = (const float*)d_in[20];
    const float* Wf1 = (const float*)d_in[21];
    const float* bf1 = (const float*)d_in[22];
    const float* Wf2 = (const float*)d_in[23];
    const float* bf2 = (const float*)d_in[24];
    float* out = (float*)d_out;

    float* actp = nullptr;
    cudaGetSymbolAddress((void**)&actp, g_act);

    const int NB_SCAN = (Nn + 1023) / 1024;   // 49
    const int EB = (Ee + 255) / 256;
    const int GB = (Nn + 63) / 64;            // gemm blocks (TM=64)
    const int AB = (Nn * Hh + 255) / 256;     // alpha blocks

    // CSR build (same graph for all 4 layers)
    zero_k<<<(Nn + 255) / 256, 256>>>();
    hist_k<<<EB, 256>>>(ei);
    scan1_k<<<NB_SCAN, 1024>>>();
    scan2_k<<<1, 64>>>();
    scan3_k<<<NB_SCAN, 1024>>>();
    fill_k<<<EB, 256>>>(ei);

    // Layer 1: 128 -> 4x8
    gemm_k<128, 32><<<GB, (32 / 4) * 8>>>(x, W1);
    alpha_k<8><<<AB, 256>>>(as1, ad1);
    epv_k<<<EB, 256>>>();
    agg_k<8><<<(Nn * 8 + 255) / 256, 256>>>(b1);

    // Layer 2: 32 -> 4x16
    gemm_k<32, 64><<<GB, (64 / 4) * 8>>>(actp, W2);
    alpha_k<16><<<AB, 256>>>(as2, ad2);
    epv_k<<<EB, 256>>>();
    agg_k<16><<<(Nn * 16 + 255) / 256, 256>>>(b2);

    // Layer 3: 64 -> 4x32
    gemm_k<64, 128><<<GB, (128 / 4) * 8>>>(actp, W3);
    alpha_k<32><<<AB, 256>>>(as3, ad3);
    epv_k<<<EB, 256>>>();
    agg_k<32><<<(Nn * 32 + 255) / 256, 256>>>(b3);

    // Layer 4: 128 -> 4x64
    gemm_k<128, 256><<<GB, (256 / 4) * 8>>>(actp, W4);
    alpha_k<64><<<AB, 256>>>(as4, ad4);
    epv_k<<<EB, 256>>>();
    agg_k<64><<<(Nn * 64 + 255) / 256, 256>>>(b4);

    // MLP head
    mlp_k<<<(Nn + 7) / 8, 256>>>(Wr, br, Wf1, bf1, Wf2, bf2, out);
}